// round 1
// baseline (speedup 1.0000x reference)
#include <cuda_runtime.h>
#include <cuda_bf16.h>

// Per-pixel dynamic 5x5 conv, channel-shared taps.
// x: [B=8, C=64, H=256, W=256] f32
// w: [25, B, 1, H, W] f32
// out[b,c,h,w] = sum_{hh,ww} xpad[b,c,h+hh,w+ww] * w[hh*5+ww, b, 0, h, w]

#define BB 8
#define CC 64
#define HH_DIM 256
#define WW_DIM 256
#define TH 16          // output tile height per block
#define TW 64          // output tile width per block
#define SMH (TH + 4)   // 20
#define SMCOLS (TW + 4) // 68 valid columns
#define SMW 72         // padded smem row stride (floats), 288B = 16B-aligned rows
#define NLOAD (SMH * SMCOLS)  // 1360

__global__ __launch_bounds__(256, 1)
void dynconv5x5_kernel(const float* __restrict__ x,
                       const float* __restrict__ wgt,
                       float* __restrict__ out) {
    __shared__ float sm[SMH * SMW];

    const int tid = threadIdx.x;
    const int tx  = tid & 15;    // 16 strips of 4 along W
    const int ty  = tid >> 4;    // 16 rows along H
    const int w0  = blockIdx.x * TW;
    const int h0  = blockIdx.y * TH;
    const int b   = blockIdx.z;

    const int oh = h0 + ty;        // this thread's output row (global)
    const int ow = w0 + tx * 4;    // this thread's first output col (global, 4-aligned)

    // ---- load the 25 per-pixel weight vectors into registers (reused for all 64 channels)
    float4 wk[25];
#pragma unroll
    for (int k = 0; k < 25; k++) {
        wk[k] = *(const float4*)&wgt[(((size_t)k * BB + b) * HH_DIM + oh) * WW_DIM + ow];
    }

    const float* xb = x   + (size_t)b * CC * HH_DIM * WW_DIM;
    float*       ob = out + (size_t)b * CC * HH_DIM * WW_DIM;

    for (int c = 0; c < CC; c++) {
        const float* xc = xb + (size_t)c * HH_DIM * WW_DIM;

        // ---- cooperative halo'd tile load (zero padding at image borders)
#pragma unroll
        for (int i = tid; i < NLOAD; i += 256) {
            int r  = i / SMCOLS;
            int cc2 = i - r * SMCOLS;
            int gh = h0 + r - 2;
            int gw = w0 + cc2 - 2;
            float v = 0.0f;
            if (gh >= 0 && gh < HH_DIM && gw >= 0 && gw < WW_DIM)
                v = xc[gh * WW_DIM + gw];
            sm[r * SMW + cc2] = v;
        }
        __syncthreads();

        // ---- 25-tap accumulation for 4 outputs (1x4 w-strip)
        float4 acc = make_float4(0.f, 0.f, 0.f, 0.f);
#pragma unroll
        for (int hh = 0; hh < 5; hh++) {
            const float* row = &sm[(ty + hh) * SMW + tx * 4];
            float4 xa = *(const float4*)(row);
            float4 xb4 = *(const float4*)(row + 4);
            float xs0 = xa.x, xs1 = xa.y, xs2 = xa.z, xs3 = xa.w;
            float xs4 = xb4.x, xs5 = xb4.y, xs6 = xb4.z, xs7 = xb4.w;
            float xsv[8] = {xs0, xs1, xs2, xs3, xs4, xs5, xs6, xs7};
#pragma unroll
            for (int ww = 0; ww < 5; ww++) {
                float4 wv = wk[hh * 5 + ww];
                acc.x = fmaf(xsv[ww + 0], wv.x, acc.x);
                acc.y = fmaf(xsv[ww + 1], wv.y, acc.y);
                acc.z = fmaf(xsv[ww + 2], wv.z, acc.z);
                acc.w = fmaf(xsv[ww + 3], wv.w, acc.w);
            }
        }

        *(float4*)&ob[(size_t)c * HH_DIM * WW_DIM + oh * WW_DIM + ow] = acc;
        __syncthreads();   // protect smem tile before next channel overwrites it
    }
}

extern "C" void kernel_launch(void* const* d_in, const int* in_sizes, int n_in,
                              void* d_out, int out_size) {
    const float* x   = (const float*)d_in[0];
    const float* wgt = (const float*)d_in[1];
    float*       out = (float*)d_out;

    dim3 grid(WW_DIM / TW, HH_DIM / TH, BB);   // 4 x 16 x 8 = 512 blocks
    dim3 block(256);
    dynconv5x5_kernel<<<grid, block>>>(x, wgt, out);
}

// round 2
// speedup vs baseline: 1.3221x; 1.3221x over previous
#include <cuda_runtime.h>
#include <cuda_bf16.h>

// Per-pixel dynamic 5x5 conv, channel-shared taps.
// x: [B=8, C=64, H=256, W=256] f32
// w: [25, B, 1, H, W] f32
// out[b,c,h,w] = sum_{hh,ww} xpad[b,c,h+hh,w+ww] * w[hh*5+ww, b, 0, h, w]
//
// Structure: CTA owns (b, 16x64 tile, half of channels). Per-pixel weights live
// in registers (reused across 32 channels). The x tile is staged through a
// double-buffered smem tile with register-staged prefetch: while computing
// channel c from buffer A, channel c+1's tile is in flight into registers
// (STS'd to buffer B at the top of the next iteration). One barrier/channel.

#define BB 8
#define HW 65536            // 256*256
#define HH_DIM 256
#define WW_DIM 256
#define TH 16               // output tile height
#define TW 64               // output tile width
#define SMH (TH + 4)        // 20
#define SMCOLS (TW + 4)     // 68 valid columns
#define SMW 72              // smem row stride (floats)
#define NLOAD (SMH * SMCOLS)  // 1360
#define NSLOT 6             // ceil(1360/256)
#define CPERCTA 32          // channels per CTA (64 split across 2 CTAs)

__global__ __launch_bounds__(256, 1)
void dynconv5x5_kernel(const float* __restrict__ x,
                       const float* __restrict__ wgt,
                       float* __restrict__ out) {
    __shared__ float sm[2][SMH * SMW];

    const int tid = threadIdx.x;
    const int tx  = tid & 15;
    const int ty  = tid >> 4;
    const int w0  = blockIdx.x * TW;
    const int h0  = blockIdx.y * TH;
    const int z   = blockIdx.z;        // 0..15
    const int b   = z >> 1;
    const int c0  = (z & 1) * CPERCTA;

    const int oh = h0 + ty;
    const int ow = w0 + tx * 4;

    // ---- per-pixel weights into registers (reused across CPERCTA channels)
    float4 wk[25];
#pragma unroll
    for (int k = 0; k < 25; k++) {
        wk[k] = *(const float4*)&wgt[(((size_t)k * BB + b) * HH_DIM + oh) * WW_DIM + ow];
    }

    // ---- precompute staging slots: gmem offset, validity, smem offset
    int  xoff[NSLOT];
    int  soff[NSLOT];
    bool vld [NSLOT];
#pragma unroll
    for (int j = 0; j < NSLOT; j++) {
        int i  = tid + j * 256;
        int r  = i / SMCOLS;
        int cc = i - r * SMCOLS;
        bool act = (i < NLOAD);
        int gh = h0 + r - 2;
        int gw = w0 + cc - 2;
        vld[j]  = act && gh >= 0 && gh < HH_DIM && gw >= 0 && gw < WW_DIM;
        xoff[j] = gh * WW_DIM + gw;                       // only used if vld
        soff[j] = act ? (r * SMW + cc) : (SMH * SMW - 1); // dead pad slot, never read
    }

    const float* xc = x   + ((size_t)b * 64 + c0) * HW;   // first channel of our range
    float*       ob = out + (((size_t)b * 64 + c0) * HW) + oh * WW_DIM + ow;

    // ---- prologue: fetch channel 0's tile into registers
    float v[NSLOT];
#pragma unroll
    for (int j = 0; j < NSLOT; j++)
        v[j] = vld[j] ? __ldg(&xc[xoff[j]]) : 0.0f;

    int buf = 0;
    for (int c = 0; c < CPERCTA; c++) {
        float* s = sm[buf];

        // commit staged registers to this channel's smem buffer
#pragma unroll
        for (int j = 0; j < NSLOT; j++)
            s[soff[j]] = v[j];
        __syncthreads();

        // issue next channel's loads; latency overlaps the compute below
        if (c + 1 < CPERCTA) {
            const float* xn = xc + (size_t)(c + 1) * HW;
#pragma unroll
            for (int j = 0; j < NSLOT; j++)
                v[j] = vld[j] ? __ldg(&xn[xoff[j]]) : 0.0f;
        }

        // ---- 25-tap accumulation for a 1x4 strip
        float4 acc = make_float4(0.f, 0.f, 0.f, 0.f);
#pragma unroll
        for (int hh = 0; hh < 5; hh++) {
            const float* row = &s[(ty + hh) * SMW + tx * 4];
            float4 xa  = *(const float4*)(row);
            float4 xb4 = *(const float4*)(row + 4);
            float xsv[8] = {xa.x, xa.y, xa.z, xa.w, xb4.x, xb4.y, xb4.z, xb4.w};
#pragma unroll
            for (int ww = 0; ww < 5; ww++) {
                float4 wv = wk[hh * 5 + ww];
                acc.x = fmaf(xsv[ww + 0], wv.x, acc.x);
                acc.y = fmaf(xsv[ww + 1], wv.y, acc.y);
                acc.z = fmaf(xsv[ww + 2], wv.z, acc.z);
                acc.w = fmaf(xsv[ww + 3], wv.w, acc.w);
            }
        }

        *(float4*)(ob + (size_t)c * HW) = acc;
        buf ^= 1;
        // no second barrier: next iteration's STS targets the other buffer,
        // whose last readers are separated by the barrier above.
    }
}

extern "C" void kernel_launch(void* const* d_in, const int* in_sizes, int n_in,
                              void* d_out, int out_size) {
    const float* x   = (const float*)d_in[0];
    const float* wgt = (const float*)d_in[1];
    float*       out = (float*)d_out;

    dim3 grid(WW_DIM / TW, HH_DIM / TH, BB * 2);   // 4 x 16 x 16 = 1024 blocks
    dim3 block(256);
    dynconv5x5_kernel<<<grid, block>>>(x, wgt, out);
}

// round 3
// speedup vs baseline: 1.7385x; 1.3150x over previous
#include <cuda_runtime.h>
#include <cuda_bf16.h>
#include <cstdint>

// Per-pixel dynamic 5x5 conv, channel-shared taps.
// x: [B=8, C=64, H=256, W=256] f32; w: [25, B, 1, H, W] f32
// out[b,c,h,w] = sum_{hh,ww} xpad[b,c,h+hh,w+ww] * w[hh*5+ww, b, 0, h, w]
//
// 256 threads/CTA, 2 px/thread (16x32 tile), weights for both pixels in 50
// registers, reused across 32 channels. x tile staged via cp.async into a
// double-buffered smem tile; 2 CTAs/SM so barriers on one CTA overlap compute
// on the other.

#define BB 8
#define HW 65536
#define HH_DIM 256
#define WW_DIM 256
#define TH 16
#define TW 32
#define SMH (TH + 4)        // 20
#define SMCOLS (TW + 4)     // 36
#define SMW 40              // padded row stride (floats); cols 36..39 never read
#define SMSZ (SMH * SMW)    // 800
#define NLOAD (SMH * SMCOLS)  // 720
#define NSLOT 3
#define CPERCTA 32

__device__ __forceinline__ void cp_async4(uint32_t saddr, const void* gaddr, int src_size) {
    asm volatile("cp.async.ca.shared.global [%0], [%1], 4, %2;"
                 :: "r"(saddr), "l"(gaddr), "r"(src_size));
}
__device__ __forceinline__ void cp_commit() {
    asm volatile("cp.async.commit_group;");
}
__device__ __forceinline__ void cp_wait_all() {
    asm volatile("cp.async.wait_group 0;");
}

__global__ __launch_bounds__(256, 2)
void dynconv5x5_kernel(const float* __restrict__ x,
                       const float* __restrict__ wgt,
                       float* __restrict__ out) {
    __shared__ float sm[2][SMSZ];

    const int tid = threadIdx.x;
    const int tx  = tid & 15;     // 16 strips of 2 along W
    const int ty  = tid >> 4;     // 16 rows
    const int w0  = blockIdx.x * TW;
    const int h0  = blockIdx.y * TH;
    const int z   = blockIdx.z;   // 0..15
    const int b   = z >> 1;
    const int c0  = (z & 1) * CPERCTA;

    const int oh = h0 + ty;
    const int ow = w0 + tx * 2;

    // ---- per-pixel weights (2 px) into 50 registers, reused for 32 channels
    float2 wk[25];
#pragma unroll
    for (int k = 0; k < 25; k++) {
        wk[k] = *(const float2*)&wgt[(((size_t)k * BB + b) * HH_DIM + oh) * WW_DIM + ow];
    }

    // ---- staging slots (hoisted): gmem offset, src-size (0 => zero-fill), smem offset
    int xoff[NSLOT];
    int ssz [NSLOT];
    int soff[NSLOT];   // in bytes
#pragma unroll
    for (int j = 0; j < NSLOT; j++) {
        int i  = tid + j * 256;
        int r  = i / SMCOLS;
        int cc = i - r * SMCOLS;
        bool act = (i < NLOAD);
        int gh = h0 + r - 2;
        int gw = w0 + cc - 2;
        bool v = act && gh >= 0 && gh < HH_DIM && gw >= 0 && gw < WW_DIM;
        xoff[j] = gh * WW_DIM + gw;
        ssz[j]  = v ? 4 : 0;
        soff[j] = (act ? (r * SMW + cc) : (SMSZ - 1)) * 4;  // pad col, never read
    }

    const float* xc = x   + ((size_t)b * 64 + c0) * HW;
    float*       ob = out + (((size_t)b * 64 + c0) * HW) + oh * WW_DIM + ow;

    const uint32_t sb0 = (uint32_t)__cvta_generic_to_shared(&sm[0][0]);
    const uint32_t sb1 = (uint32_t)__cvta_generic_to_shared(&sm[1][0]);

    // ---- prologue: stage channel 0 into buffer 0
#pragma unroll
    for (int j = 0; j < NSLOT; j++)
        cp_async4(sb0 + soff[j], xc + xoff[j], ssz[j]);
    cp_commit();
    cp_wait_all();
    __syncthreads();

    int buf = 0;
    for (int c = 0; c < CPERCTA; c++) {
        // stage next channel into the other buffer (overlaps compute below)
        if (c + 1 < CPERCTA) {
            const float* xn = xc + (size_t)(c + 1) * HW;
            const uint32_t sbn = (buf == 0) ? sb1 : sb0;
#pragma unroll
            for (int j = 0; j < NSLOT; j++)
                cp_async4(sbn + soff[j], xn + xoff[j], ssz[j]);
            cp_commit();
        }

        const float* s = sm[buf];

        // ---- 25-tap accumulation for a 1x2 strip
        float2 acc = make_float2(0.f, 0.f);
#pragma unroll
        for (int hh = 0; hh < 5; hh++) {
            const float* row = &s[(ty + hh) * SMW + tx * 2];
            float2 a0 = *(const float2*)(row);
            float2 a1 = *(const float2*)(row + 2);
            float2 a2 = *(const float2*)(row + 4);
            float xs[6] = {a0.x, a0.y, a1.x, a1.y, a2.x, a2.y};
#pragma unroll
            for (int ww = 0; ww < 5; ww++) {
                float2 wv = wk[hh * 5 + ww];
                acc.x = fmaf(xs[ww + 0], wv.x, acc.x);
                acc.y = fmaf(xs[ww + 1], wv.y, acc.y);
            }
        }

        *(float2*)(ob + (size_t)c * HW) = acc;

        if (c + 1 < CPERCTA) cp_wait_all();
        __syncthreads();
        buf ^= 1;
    }
}

extern "C" void kernel_launch(void* const* d_in, const int* in_sizes, int n_in,
                              void* d_out, int out_size) {
    const float* x   = (const float*)d_in[0];
    const float* wgt = (const float*)d_in[1];
    float*       out = (float*)d_out;

    dim3 grid(WW_DIM / TW, HH_DIM / TH, BB * 2);   // 8 x 16 x 16 = 2048 blocks
    dim3 block(256);
    dynconv5x5_kernel<<<grid, block>>>(x, wgt, out);
}

// round 4
// speedup vs baseline: 2.1817x; 1.2549x over previous
#include <cuda_runtime.h>
#include <cuda_bf16.h>
#include <cstdint>

// Per-pixel dynamic 5x5 conv, channel-shared taps.
// x: [B=8, C=64, H=256, W=256] f32; w: [25, B, 1, H, W] f32
// out[b,c,h,w] = sum_{hh,ww} xpad[b,c,h+hh,w+ww] * w[hh*5+ww, b, 0, h, w]
//
// 256 threads/CTA, 2 px/thread (16x32 tile), 50 weight regs reused across 32
// channels. x staged via cp.async into double-buffered smem; 3 CTAs/SM so
// per-CTA barriers/waits are hidden by sibling CTAs. 4 independent FMA chains.

#define BB 8
#define HW 65536
#define HH_DIM 256
#define WW_DIM 256
#define TH 16
#define TW 32
#define SMH (TH + 4)        // 20
#define SMCOLS (TW + 4)     // 36
#define SMW 40              // padded row stride (floats); cols 36..39 never read
#define SMSZ (SMH * SMW)    // 800
#define NLOAD (SMH * SMCOLS)  // 720
#define NSLOT 3
#define CPERCTA 32

__device__ __forceinline__ void cp_async4(uint32_t saddr, const void* gaddr, int src_size) {
    asm volatile("cp.async.ca.shared.global [%0], [%1], 4, %2;"
                 :: "r"(saddr), "l"(gaddr), "r"(src_size));
}
__device__ __forceinline__ void cp_commit() {
    asm volatile("cp.async.commit_group;");
}
__device__ __forceinline__ void cp_wait_all() {
    asm volatile("cp.async.wait_group 0;");
}

__global__ __launch_bounds__(256, 3)
void dynconv5x5_kernel(const float* __restrict__ x,
                       const float* __restrict__ wgt,
                       float* __restrict__ out) {
    __shared__ float sm[2][SMSZ];

    const int tid = threadIdx.x;
    const int tx  = tid & 15;
    const int ty  = tid >> 4;
    const int w0  = blockIdx.x * TW;
    const int h0  = blockIdx.y * TH;
    const int z   = blockIdx.z;
    const int b   = z >> 1;
    const int c0  = (z & 1) * CPERCTA;

    const int oh = h0 + ty;
    const int ow = w0 + tx * 2;

    // ---- per-pixel weights (2 px) into 50 registers
    float2 wk[25];
#pragma unroll
    for (int k = 0; k < 25; k++) {
        wk[k] = *(const float2*)&wgt[(((size_t)k * BB + b) * HH_DIM + oh) * WW_DIM + ow];
    }

    // ---- hoisted staging slots
    int xoff[NSLOT];
    int ssz [NSLOT];
    int soff[NSLOT];   // bytes
#pragma unroll
    for (int j = 0; j < NSLOT; j++) {
        int i  = tid + j * 256;
        int r  = i / SMCOLS;
        int cc = i - r * SMCOLS;
        bool act = (i < NLOAD);
        int gh = h0 + r - 2;
        int gw = w0 + cc - 2;
        bool v = act && gh >= 0 && gh < HH_DIM && gw >= 0 && gw < WW_DIM;
        xoff[j] = gh * WW_DIM + gw;
        ssz[j]  = v ? 4 : 0;
        soff[j] = (act ? (r * SMW + cc) : (SMSZ - 1)) * 4;
    }

    const float* xc = x   + ((size_t)b * 64 + c0) * HW;
    float*       ob = out + (((size_t)b * 64 + c0) * HW) + oh * WW_DIM + ow;

    const uint32_t sb0 = (uint32_t)__cvta_generic_to_shared(&sm[0][0]);
    const uint32_t sb1 = (uint32_t)__cvta_generic_to_shared(&sm[1][0]);

    // prologue: stage channel 0 into buffer 0
#pragma unroll
    for (int j = 0; j < NSLOT; j++)
        cp_async4(sb0 + soff[j], xc + xoff[j], ssz[j]);
    cp_commit();
    cp_wait_all();
    __syncthreads();

    int buf = 0;
    for (int c = 0; c < CPERCTA; c++) {
        if (c + 1 < CPERCTA) {
            const float* xn = xc + (size_t)(c + 1) * HW;
            const uint32_t sbn = (buf == 0) ? sb1 : sb0;
#pragma unroll
            for (int j = 0; j < NSLOT; j++)
                cp_async4(sbn + soff[j], xn + xoff[j], ssz[j]);
            cp_commit();
        }

        const float* s = sm[buf];

        // ---- 25 taps, 2 px, 4 independent accumulator chains
        float ax0 = 0.f, ax1 = 0.f;   // px0: even/odd taps
        float ay0 = 0.f, ay1 = 0.f;   // px1: even/odd taps
#pragma unroll
        for (int hh = 0; hh < 5; hh++) {
            const float* row = &s[(ty + hh) * SMW + tx * 2];
            float2 a0 = *(const float2*)(row);
            float2 a1 = *(const float2*)(row + 2);
            float2 a2 = *(const float2*)(row + 4);
            float xs[6] = {a0.x, a0.y, a1.x, a1.y, a2.x, a2.y};
#pragma unroll
            for (int ww = 0; ww < 5; ww++) {
                float2 wv = wk[hh * 5 + ww];
                if (((hh * 5 + ww) & 1) == 0) {
                    ax0 = fmaf(xs[ww + 0], wv.x, ax0);
                    ay0 = fmaf(xs[ww + 1], wv.y, ay0);
                } else {
                    ax1 = fmaf(xs[ww + 0], wv.x, ax1);
                    ay1 = fmaf(xs[ww + 1], wv.y, ay1);
                }
            }
        }

        float2 acc = make_float2(ax0 + ax1, ay0 + ay1);
        *(float2*)(ob + (size_t)c * HW) = acc;

        if (c + 1 < CPERCTA) cp_wait_all();
        __syncthreads();
        buf ^= 1;
    }
}

extern "C" void kernel_launch(void* const* d_in, const int* in_sizes, int n_in,
                              void* d_out, int out_size) {
    const float* x   = (const float*)d_in[0];
    const float* wgt = (const float*)d_in[1];
    float*       out = (float*)d_out;

    dim3 grid(WW_DIM / TW, HH_DIM / TH, BB * 2);   // 8 x 16 x 16 = 2048 blocks
    dim3 block(256);
    dynconv5x5_kernel<<<grid, block>>>(x, wgt, out);
}

// round 5
// speedup vs baseline: 2.8192x; 1.2922x over previous
#include <cuda_runtime.h>
#include <cuda_bf16.h>
#include <cstdint>

// Per-pixel dynamic 5x5 conv, channel-shared taps.
// x: [B=8, C=64, H=256, W=256] f32; w: [25, B, 1, H, W] f32
//
// 2x2 pixel quad per thread (36B LDS per output px, 40% less than 1x2),
// 128 threads/CTA (16x32 tile), 100 weight regs reused across 32 channels,
// 4-stage cp.async ring (prefetch distance 2), one barrier per channel,
// 3 CTAs/SM.

#define BB 8
#define HW 65536
#define HH_DIM 256
#define WW_DIM 256
#define TH 16
#define TW 32
#define SMH (TH + 4)          // 20
#define SMCOLS (TW + 4)       // 36
#define SMW 40                // row stride (floats)
#define SMSZ (SMH * SMW)      // 800 floats per stage
#define NLOAD (SMH * SMCOLS)  // 720
#define NSLOT 6               // ceil(720/128)
#define CPERCTA 32
#define NSTAGE 4

__device__ __forceinline__ void cp_async4(uint32_t saddr, const void* gaddr, int src_size) {
    asm volatile("cp.async.ca.shared.global [%0], [%1], 4, %2;"
                 :: "r"(saddr), "l"(gaddr), "r"(src_size));
}
__device__ __forceinline__ void cp_commit() {
    asm volatile("cp.async.commit_group;");
}
template <int N>
__device__ __forceinline__ void cp_wait() {
    asm volatile("cp.async.wait_group %0;" :: "n"(N));
}

__global__ __launch_bounds__(128, 3)
void dynconv5x5_kernel(const float* __restrict__ x,
                       const float* __restrict__ wgt,
                       float* __restrict__ out) {
    __shared__ float sm[NSTAGE][SMSZ];

    const int tid = threadIdx.x;
    const int qx  = tid & 15;     // 16 quads along W
    const int qy  = tid >> 4;     // 8 quads along H
    const int w0  = blockIdx.x * TW;
    const int h0  = blockIdx.y * TH;
    const int z   = blockIdx.z;
    const int b   = z >> 1;
    const int c0  = (z & 1) * CPERCTA;

    const int oh = h0 + qy * 2;   // top row of quad
    const int ow = w0 + qx * 2;   // left col of quad

    // ---- per-pixel weights for the 2x2 quad (100 regs), reused for 32 channels
    float2 wt[25];   // top row pixels
    float2 wb[25];   // bottom row pixels
#pragma unroll
    for (int k = 0; k < 25; k++) {
        const float* wp = &wgt[(((size_t)k * BB + b) * HH_DIM + oh) * WW_DIM + ow];
        wt[k] = *(const float2*)(wp);
        wb[k] = *(const float2*)(wp + WW_DIM);
    }

    // ---- hoisted staging slots
    int xoff[NSLOT];
    int ssz [NSLOT];
    int soff[NSLOT];   // bytes, relative to stage base
#pragma unroll
    for (int j = 0; j < NSLOT; j++) {
        int i  = tid + j * 128;
        int r  = i / SMCOLS;
        int cc = i - r * SMCOLS;
        bool act = (i < NLOAD);
        int gh = h0 + r - 2;
        int gw = w0 + cc - 2;
        bool v = act && gh >= 0 && gh < HH_DIM && gw >= 0 && gw < WW_DIM;
        xoff[j] = gh * WW_DIM + gw;
        ssz[j]  = v ? 4 : 0;
        soff[j] = (act ? (r * SMW + cc) : (SMSZ - 1)) * 4;  // dead pad slot, never read
    }

    const float* xc = x   + ((size_t)b * 64 + c0) * HW;
    float*       ob = out + (((size_t)b * 64 + c0) * HW) + oh * WW_DIM + ow;

    uint32_t sb[NSTAGE];
#pragma unroll
    for (int s = 0; s < NSTAGE; s++)
        sb[s] = (uint32_t)__cvta_generic_to_shared(&sm[s][0]);

    // ---- prologue: stage channels 0 and 1
#pragma unroll
    for (int p = 0; p < 2; p++) {
        const float* xp = xc + (size_t)p * HW;
#pragma unroll
        for (int j = 0; j < NSLOT; j++)
            cp_async4(sb[p] + soff[j], xp + xoff[j], ssz[j]);
        cp_commit();
    }

    for (int c = 0; c < CPERCTA; c++) {
        if (c + 2 < CPERCTA) cp_wait<1>(); else cp_wait<0>();
        __syncthreads();   // channel c's tile visible to all

        const float* s = sm[c & (NSTAGE - 1)];

        // ---- 25 taps x 4 pixels, 8 accumulator chains
        float at0e = 0.f, at0o = 0.f, at1e = 0.f, at1o = 0.f;  // top px (even/odd taps)
        float ab0e = 0.f, ab0o = 0.f, ab1e = 0.f, ab1o = 0.f;  // bottom px
#pragma unroll
        for (int r = 0; r < 6; r++) {
            const float* row = &s[(qy * 2 + r) * SMW + qx * 2];
            float2 a0 = *(const float2*)(row);
            float2 a1 = *(const float2*)(row + 2);
            float2 a2 = *(const float2*)(row + 4);
            float xs[6] = {a0.x, a0.y, a1.x, a1.y, a2.x, a2.y};
            if (r < 5) {
#pragma unroll
                for (int ww = 0; ww < 5; ww++) {
                    float2 wv = wt[r * 5 + ww];
                    if (((r * 5 + ww) & 1) == 0) {
                        at0e = fmaf(xs[ww + 0], wv.x, at0e);
                        at1e = fmaf(xs[ww + 1], wv.y, at1e);
                    } else {
                        at0o = fmaf(xs[ww + 0], wv.x, at0o);
                        at1o = fmaf(xs[ww + 1], wv.y, at1o);
                    }
                }
            }
            if (r >= 1) {
#pragma unroll
                for (int ww = 0; ww < 5; ww++) {
                    int k = (r - 1) * 5 + ww;
                    float2 wv = wb[k];
                    if ((k & 1) == 0) {
                        ab0e = fmaf(xs[ww + 0], wv.x, ab0e);
                        ab1e = fmaf(xs[ww + 1], wv.y, ab1e);
                    } else {
                        ab0o = fmaf(xs[ww + 0], wv.x, ab0o);
                        ab1o = fmaf(xs[ww + 1], wv.y, ab1o);
                    }
                }
            }
        }

        float* o = ob + (size_t)c * HW;
        *(float2*)(o)          = make_float2(at0e + at0o, at1e + at1o);
        *(float2*)(o + WW_DIM) = make_float2(ab0e + ab0o, ab1e + ab1o);

        // stage channel c+2 into its ring slot (distance-4 buffer reuse is
        // protected by the per-iteration barrier above)
        if (c + 2 < CPERCTA) {
            const float* xn = xc + (size_t)(c + 2) * HW;
            const uint32_t sbn = sb[(c + 2) & (NSTAGE - 1)];
#pragma unroll
            for (int j = 0; j < NSLOT; j++)
                cp_async4(sbn + soff[j], xn + xoff[j], ssz[j]);
            cp_commit();
        }
    }
}

extern "C" void kernel_launch(void* const* d_in, const int* in_sizes, int n_in,
                              void* d_out, int out_size) {
    const float* x   = (const float*)d_in[0];
    const float* wgt = (const float*)d_in[1];
    float*       out = (float*)d_out;

    dim3 grid(WW_DIM / TW, HH_DIM / TH, BB * 2);   // 8 x 16 x 16 = 2048 blocks
    dim3 block(128);
    dynconv5x5_kernel<<<grid, block>>>(x, wgt, out);
}

// round 6
// speedup vs baseline: 2.9794x; 1.0568x over previous
#include <cuda_runtime.h>
#include <cuda_bf16.h>
#include <cstdint>

// Per-pixel dynamic 5x5 conv, channel-shared taps.
// x: [B=8, C=64, H=256, W=256] f32; w: [25, B, 1, H, W] f32
//
// 2x2 pixel quad per thread, 128 threads/CTA (16x32 tile), 100 weight regs
// (as 50 packed f32x2 pairs) reused across 32 channels. All tap math uses
// fma.rn.f32x2 (FFMA2): 50 packed FMAs/thread/channel instead of 100 FFMA.
// 4-stage cp.async ring (distance 2), one barrier/channel, 3 CTAs/SM.

#define BB 8
#define HW 65536
#define HH_DIM 256
#define WW_DIM 256
#define TH 16
#define TW 32
#define SMH (TH + 4)          // 20
#define SMCOLS (TW + 4)       // 36
#define SMW 40                // row stride (floats)
#define SMSZ (SMH * SMW)      // 800 floats per stage
#define NLOAD (SMH * SMCOLS)  // 720
#define NSLOT 6
#define CPERCTA 32
#define NSTAGE 4

__device__ __forceinline__ void cp_async4(uint32_t saddr, const void* gaddr, int src_size) {
    asm volatile("cp.async.ca.shared.global [%0], [%1], 4, %2;"
                 :: "r"(saddr), "l"(gaddr), "r"(src_size));
}
__device__ __forceinline__ void cp_commit() {
    asm volatile("cp.async.commit_group;");
}
template <int N>
__device__ __forceinline__ void cp_wait() {
    asm volatile("cp.async.wait_group %0;" :: "n"(N));
}

// ---- packed fp32x2 helpers ----
__device__ __forceinline__ uint64_t lds64(uint32_t a) {
    uint64_t v; asm volatile("ld.shared.b64 %0, [%1];" : "=l"(v) : "r"(a)); return v;
}
__device__ __forceinline__ void ffma2(uint64_t& d, uint64_t a, uint64_t b) {
    asm("fma.rn.f32x2 %0, %1, %2, %0;" : "+l"(d) : "l"(a), "l"(b));
}
__device__ __forceinline__ uint64_t addf32x2(uint64_t a, uint64_t b) {
    uint64_t r; asm("add.rn.f32x2 %0, %1, %2;" : "=l"(r) : "l"(a), "l"(b)); return r;
}
__device__ __forceinline__ uint64_t pack2(uint32_t lo, uint32_t hi) {
    uint64_t r; asm("mov.b64 %0, {%1, %2};" : "=l"(r) : "r"(lo), "r"(hi)); return r;
}
__device__ __forceinline__ void unpack2(uint64_t v, uint32_t& lo, uint32_t& hi) {
    asm("mov.b64 {%0, %1}, %2;" : "=r"(lo), "=r"(hi) : "l"(v));
}

__global__ __launch_bounds__(128, 3)
void dynconv5x5_kernel(const float* __restrict__ x,
                       const float* __restrict__ wgt,
                       float* __restrict__ out) {
    __shared__ float sm[NSTAGE][SMSZ];

    const int tid = threadIdx.x;
    const int qx  = tid & 15;
    const int qy  = tid >> 4;
    const int w0  = blockIdx.x * TW;
    const int h0  = blockIdx.y * TH;
    const int z   = blockIdx.z;
    const int b   = z >> 1;
    const int c0  = (z & 1) * CPERCTA;

    const int oh = h0 + qy * 2;
    const int ow = w0 + qx * 2;   // even -> 8B aligned everywhere

    // ---- quad weights as packed pairs: wt[k]={w(px0),w(px1)} top row, wb bottom
    uint64_t wt[25], wb[25];
#pragma unroll
    for (int k = 0; k < 25; k++) {
        const float* wp = &wgt[(((size_t)k * BB + b) * HH_DIM + oh) * WW_DIM + ow];
        wt[k] = *(const uint64_t*)(wp);
        wb[k] = *(const uint64_t*)(wp + WW_DIM);
    }

    // ---- hoisted staging slots
    int xoff[NSLOT];
    int ssz [NSLOT];
    int soff[NSLOT];   // bytes
#pragma unroll
    for (int j = 0; j < NSLOT; j++) {
        int i  = tid + j * 128;
        int r  = i / SMCOLS;
        int cc = i - r * SMCOLS;
        bool act = (i < NLOAD);
        int gh = h0 + r - 2;
        int gw = w0 + cc - 2;
        bool v = act && gh >= 0 && gh < HH_DIM && gw >= 0 && gw < WW_DIM;
        xoff[j] = gh * WW_DIM + gw;
        ssz[j]  = v ? 4 : 0;
        soff[j] = (act ? (r * SMW + cc) : (SMSZ - 1)) * 4;
    }

    const float* xc = x   + ((size_t)b * 64 + c0) * HW;
    float*       ob = out + (((size_t)b * 64 + c0) * HW) + oh * WW_DIM + ow;

    // per-stage lane base addresses for compute reads
    const uint32_t laneoff = ((qy * 2) * SMW + qx * 2) * 4;
    uint32_t sb[NSTAGE], sab[NSTAGE];
#pragma unroll
    for (int s = 0; s < NSTAGE; s++) {
        sb[s]  = (uint32_t)__cvta_generic_to_shared(&sm[s][0]);
        sab[s] = sb[s] + laneoff;
    }

    // ---- prologue: stage channels 0 and 1
#pragma unroll
    for (int p = 0; p < 2; p++) {
        const float* xp = xc + (size_t)p * HW;
#pragma unroll
        for (int j = 0; j < NSLOT; j++)
            cp_async4(sb[p] + soff[j], xp + xoff[j], ssz[j]);
        cp_commit();
    }

#pragma unroll 4
    for (int c = 0; c < CPERCTA; c++) {
        if (c + 2 < CPERCTA) cp_wait<1>(); else cp_wait<0>();
        __syncthreads();

        const uint32_t sbase = sab[c & (NSTAGE - 1)];

        // ---- 25 taps x 4 px via packed f32x2: 4 packed accumulator chains
        uint64_t at_e = 0, at_o = 0, ab_e = 0, ab_o = 0;
#pragma unroll
        for (int r = 0; r < 6; r++) {
            uint32_t base = sbase + r * (SMW * 4);
            uint64_t p0 = lds64(base);        // {x0,x1}
            uint64_t p2 = lds64(base + 8);    // {x2,x3}
            uint64_t p4 = lds64(base + 16);   // {x4,x5}
            uint32_t x0, x1, x2, x3, x4, x5;
            unpack2(p0, x0, x1);
            unpack2(p2, x2, x3);
            unpack2(p4, x4, x5);
            uint64_t p1 = pack2(x1, x2);      // {x1,x2}
            uint64_t p3 = pack2(x3, x4);      // {x3,x4}
            uint64_t P[5] = {p0, p1, p2, p3, p4};
            if (r < 5) {
#pragma unroll
                for (int ww = 0; ww < 5; ww++) {
                    int k = r * 5 + ww;
                    ffma2((k & 1) ? at_o : at_e, P[ww], wt[k]);
                }
            }
            if (r >= 1) {
#pragma unroll
                for (int ww = 0; ww < 5; ww++) {
                    int k = (r - 1) * 5 + ww;
                    ffma2((k & 1) ? ab_o : ab_e, P[ww], wb[k]);
                }
            }
        }

        float* o = ob + (size_t)c * HW;
        *(uint64_t*)(o)          = addf32x2(at_e, at_o);
        *(uint64_t*)(o + WW_DIM) = addf32x2(ab_e, ab_o);

        if (c + 2 < CPERCTA) {
            const float* xn = xc + (size_t)(c + 2) * HW;
            const uint32_t sbn = sb[(c + 2) & (NSTAGE - 1)];
#pragma unroll
            for (int j = 0; j < NSLOT; j++)
                cp_async4(sbn + soff[j], xn + xoff[j], ssz[j]);
            cp_commit();
        }
    }
}

extern "C" void kernel_launch(void* const* d_in, const int* in_sizes, int n_in,
                              void* d_out, int out_size) {
    const float* x   = (const float*)d_in[0];
    const float* wgt = (const float*)d_in[1];
    float*       out = (float*)d_out;

    dim3 grid(WW_DIM / TW, HH_DIM / TH, BB * 2);   // 2048 blocks
    dim3 block(128);
    dynconv5x5_kernel<<<grid, block>>>(x, wgt, out);
}